// round 2
// baseline (speedup 1.0000x reference)
#include <cuda_runtime.h>
#include <math.h>

#define S4 4
#define CD 512
#define KD 128
#define HW 1024
#define NM 16384
#define CE 16
#define TAU_INV 30.0f

// ---------------- scratch (device globals; no allocation allowed) ----------------
__device__ float g_wq_self[S4 * HW * KD];          // [s][n][d]      2 MB
__device__ float g_sc[S4 * HW * HW];               // self probs    16 MB
__device__ float g_t[S4 * CD * HW];                // [s][c][n]      8 MB
__device__ float g_wq_cross[S4 * HW * KD];         // [s][n][d]
__device__ float g_wk_cross[S4 * NM * KD];         // [s][m][d]     32 MB
__device__ float g_part[4 * S4 * HW * 18];         // [ks][s][q][16 out + m + l]

// ================= projection + L2 normalize =================
// in layout: [(f*S + s)*CD + c]*HW + n  (token index n contiguous)
// out layout: [s][token][d], token = f*1024 + n, d in [0,128)
__global__ __launch_bounds__(256) void proj_kernel(
    const float* __restrict__ in, const float* __restrict__ W,
    const float* __restrict__ bias, float* __restrict__ out, int NT) {
  __shared__ float As[32][33];    // [cc][tok]
  __shared__ float Ws[128][33];   // [d][cc]
  __shared__ float Ys[32][129];   // [tok][d]
  int s = blockIdx.y;
  int tg0 = blockIdx.x * 32;
  int f = tg0 >> 10;
  int n0 = tg0 & 1023;
  const float* inb = in + ((size_t)(f * S4 + s)) * CD * HW + n0;
  int t = threadIdx.x;
  int tgq = t & 7;     // token group (4 tokens each)
  int dg  = t >> 3;    // d group (4 d each)
  float acc[4][4] = {};
  for (int c0 = 0; c0 < CD; c0 += 32) {
    int idx = t;
    #pragma unroll
    for (int r = 0; r < 4; r++, idx += 256) {
      int cc = idx >> 5, tok = idx & 31;
      As[cc][tok] = inb[(size_t)(c0 + cc) * HW + tok];
    }
    idx = t;
    #pragma unroll
    for (int r = 0; r < 16; r++, idx += 256) {
      int d = idx >> 5, cc = idx & 31;
      Ws[d][cc] = W[d * CD + c0 + cc];
    }
    __syncthreads();
    #pragma unroll 8
    for (int k = 0; k < 32; k++) {
      float a[4], wv[4];
      #pragma unroll
      for (int i = 0; i < 4; i++) a[i] = As[k][tgq * 4 + i];
      #pragma unroll
      for (int j = 0; j < 4; j++) wv[j] = Ws[dg * 4 + j][k];
      #pragma unroll
      for (int i = 0; i < 4; i++)
        #pragma unroll
        for (int j = 0; j < 4; j++)
          acc[i][j] = fmaf(a[i], wv[j], acc[i][j]);
    }
    __syncthreads();
  }
  #pragma unroll
  for (int j = 0; j < 4; j++) {
    float bb = bias[dg * 4 + j];
    #pragma unroll
    for (int i = 0; i < 4; i++)
      Ys[tgq * 4 + i][dg * 4 + j] = acc[i][j] + bb;
  }
  __syncthreads();
  int warp = t >> 5, lane = t & 31;
  #pragma unroll
  for (int r = 0; r < 4; r++) {
    int tt = warp * 4 + r;
    float v0 = Ys[tt][lane], v1 = Ys[tt][lane + 32];
    float v2 = Ys[tt][lane + 64], v3 = Ys[tt][lane + 96];
    float ss = v0 * v0 + v1 * v1 + v2 * v2 + v3 * v3;
    #pragma unroll
    for (int o = 16; o; o >>= 1) ss += __shfl_xor_sync(0xffffffffu, ss, o);
    float scl = 1.0f / fmaxf(sqrtf(ss), 1e-12f);
    float* ob = out + ((size_t)s * NT + tg0 + tt) * KD;
    ob[lane] = v0 * scl; ob[lane + 32] = v1 * scl;
    ob[lane + 64] = v2 * scl; ob[lane + 96] = v3 * scl;
  }
}

// ================= self-attention raw scores (x30) =================
__global__ __launch_bounds__(256) void self_scores_kernel(
    const float* __restrict__ wq, float* __restrict__ sc) {
  __shared__ float QK[2][64][65];
  int s = blockIdx.z;
  int q0 = blockIdx.x * 64, k0 = blockIdx.y * 64;
  const float* base = wq + (size_t)s * HW * KD;
  int t = threadIdx.x;
  int qg = t & 15, kg = t >> 4;
  float acc[4][4] = {};
  for (int d0 = 0; d0 < KD; d0 += 64) {
    int idx = t;
    #pragma unroll
    for (int r = 0; r < 16; r++, idx += 256) {
      int row = idx >> 6, dd = idx & 63;
      QK[0][row][dd] = base[(size_t)(q0 + row) * KD + d0 + dd];
      QK[1][row][dd] = base[(size_t)(k0 + row) * KD + d0 + dd];
    }
    __syncthreads();
    #pragma unroll 8
    for (int k = 0; k < 64; k++) {
      float a[4], b[4];
      #pragma unroll
      for (int i = 0; i < 4; i++) a[i] = QK[0][qg * 4 + i][k];
      #pragma unroll
      for (int j = 0; j < 4; j++) b[j] = QK[1][kg * 4 + j][k];
      #pragma unroll
      for (int i = 0; i < 4; i++)
        #pragma unroll
        for (int j = 0; j < 4; j++)
          acc[i][j] = fmaf(a[i], b[j], acc[i][j]);
    }
    __syncthreads();
  }
  float* Cs = &QK[0][0][0];   // reuse as [64][65]
  #pragma unroll
  for (int i = 0; i < 4; i++)
    #pragma unroll
    for (int j = 0; j < 4; j++)
      Cs[(qg * 4 + i) * 65 + kg * 4 + j] = acc[i][j] * TAU_INV;
  __syncthreads();
  int idx = t;
  #pragma unroll
  for (int r = 0; r < 16; r++, idx += 256) {
    int row = idx >> 6, col = idx & 63;
    sc[((size_t)s * HW + q0 + row) * HW + k0 + col] = Cs[row * 65 + col];
  }
}

// ================= row softmax over 1024 =================
__global__ __launch_bounds__(256) void softmax_kernel(float* __restrict__ sc) {
  __shared__ float redm[8];
  __shared__ float reds[8];
  float* p = sc + (size_t)blockIdx.x * HW;
  int t = threadIdx.x, lane = t & 31, warp = t >> 5;
  float v0 = p[t], v1 = p[t + 256], v2 = p[t + 512], v3 = p[t + 768];
  float mx = fmaxf(fmaxf(v0, v1), fmaxf(v2, v3));
  #pragma unroll
  for (int o = 16; o; o >>= 1) mx = fmaxf(mx, __shfl_xor_sync(0xffffffffu, mx, o));
  if (lane == 0) redm[warp] = mx;
  __syncthreads();
  mx = redm[0];
  #pragma unroll
  for (int i = 1; i < 8; i++) mx = fmaxf(mx, redm[i]);
  v0 = __expf(v0 - mx); v1 = __expf(v1 - mx);
  v2 = __expf(v2 - mx); v3 = __expf(v3 - mx);
  float sum = v0 + v1 + v2 + v3;
  #pragma unroll
  for (int o = 16; o; o >>= 1) sum += __shfl_xor_sync(0xffffffffu, sum, o);
  if (lane == 0) reds[warp] = sum;
  __syncthreads();
  float tot = reds[0];
  #pragma unroll
  for (int i = 1; i < 8; i++) tot += reds[i];
  float inv = 1.0f / tot;
  p[t] = v0 * inv; p[t + 256] = v1 * inv;
  p[t + 512] = v2 * inv; p[t + 768] = v3 * inv;
}

// ================= self P.V + residual =================
// out g_t[s][c][n] = tgt[s][c][n] + sum_m P[s][n][m] * tgt[s][c][m]
__global__ __launch_bounds__(256) void pv_self_kernel(
    const float* __restrict__ sc, const float* __restrict__ tgt,
    float* __restrict__ tout) {
  __shared__ float As[64][33];   // [n][m]
  __shared__ float Bs[32][65];   // [m][c]
  __shared__ float Cs[64 * 65];  // [n][c] flat
  int s = blockIdx.z;
  int n0 = blockIdx.x * 64, c0 = blockIdx.y * 64;
  const float* P = sc + (size_t)s * HW * HW;
  const float* V = tgt + (size_t)s * CD * HW;
  int t = threadIdx.x;
  int ng = t & 15, cg = t >> 4;
  float acc[4][4] = {};
  for (int m0 = 0; m0 < HW; m0 += 32) {
    int idx = t;
    #pragma unroll
    for (int r = 0; r < 8; r++, idx += 256) {
      int n = idx >> 5, m = idx & 31;
      As[n][m] = P[(size_t)(n0 + n) * HW + m0 + m];
    }
    idx = t;
    #pragma unroll
    for (int r = 0; r < 8; r++, idx += 256) {
      int c = idx >> 5, m = idx & 31;
      Bs[m][c] = V[(size_t)(c0 + c) * HW + m0 + m];
    }
    __syncthreads();
    #pragma unroll 8
    for (int k = 0; k < 32; k++) {
      float a[4], b[4];
      #pragma unroll
      for (int i = 0; i < 4; i++) a[i] = As[ng * 4 + i][k];
      #pragma unroll
      for (int j = 0; j < 4; j++) b[j] = Bs[k][cg * 4 + j];
      #pragma unroll
      for (int i = 0; i < 4; i++)
        #pragma unroll
        for (int j = 0; j < 4; j++)
          acc[i][j] = fmaf(a[i], b[j], acc[i][j]);
    }
    __syncthreads();
  }
  #pragma unroll
  for (int i = 0; i < 4; i++)
    #pragma unroll
    for (int j = 0; j < 4; j++)
      Cs[(ng * 4 + i) * 65 + cg * 4 + j] = acc[i][j];
  __syncthreads();
  int idx = t;
  #pragma unroll
  for (int r = 0; r < 16; r++, idx += 256) {
    int c = idx >> 6, n = idx & 63;
    size_t g = (size_t)(s * CD + c0 + c) * HW + n0 + n;
    tout[g] = tgt[g] + Cs[n * 65 + c];
  }
}

// ================= instance norm (per (s,c) over 1024 tokens) =================
__global__ __launch_bounds__(256) void instnorm_kernel(float* __restrict__ x) {
  __shared__ float redS[8];
  __shared__ float redQ[8];
  float* p = x + (size_t)blockIdx.x * HW;
  int t = threadIdx.x, lane = t & 31, warp = t >> 5;
  float v0 = p[t], v1 = p[t + 256], v2 = p[t + 512], v3 = p[t + 768];
  float sum = v0 + v1 + v2 + v3;
  float sq = v0 * v0 + v1 * v1 + v2 * v2 + v3 * v3;
  #pragma unroll
  for (int o = 16; o; o >>= 1) {
    sum += __shfl_xor_sync(0xffffffffu, sum, o);
    sq  += __shfl_xor_sync(0xffffffffu, sq, o);
  }
  if (lane == 0) { redS[warp] = sum; redQ[warp] = sq; }
  __syncthreads();
  sum = redS[0]; sq = redQ[0];
  #pragma unroll
  for (int i = 1; i < 8; i++) { sum += redS[i]; sq += redQ[i]; }
  float mean = sum * (1.0f / HW);
  float var = sq * (1.0f / HW) - mean * mean;
  float rstd = rsqrtf(var + 1e-5f);
  p[t]       = (v0 - mean) * rstd;
  p[t + 256] = (v1 - mean) * rstd;
  p[t + 512] = (v2 - mean) * rstd;
  p[t + 768] = (v3 - mean) * rstd;
}

// ================= cross attention: flash-style with split-K =================
#define DOT4(ACC, A, B) do { \
  ACC = fmaf((A).x, (B).x, ACC); ACC = fmaf((A).y, (B).y, ACC); \
  ACC = fmaf((A).z, (B).z, ACC); ACC = fmaf((A).w, (B).w, ACC); } while (0)

__global__ __launch_bounds__(256) void cross_attn_kernel(
    const float* __restrict__ wq, const float* __restrict__ wk,
    const float* __restrict__ pe, float* __restrict__ part) {
  extern __shared__ float sm[];
  float* Qs = sm;                    // [64][132]
  float* Ks = Qs + 64 * 132;         // [64][132]
  float* Ps = Ks + 64 * 132;         // [64][65]
  float* Vs = Ps + 64 * 65;          // [64][16]
  float* Os = Vs + 64 * 16;          // [64][16]
  float* Om = Os + 64 * 16;          // [64]
  float* Ol = Om + 64;               // [64]
  int qt = blockIdx.x, s = blockIdx.y, ksp = blockIdx.z;
  int q0 = qt * 64;
  int t = threadIdx.x, lane = t & 31, warp = t >> 5;
  {
    int idx = t;
    #pragma unroll
    for (int r = 0; r < 32; r++, idx += 256) {
      int q = idx >> 7, d = idx & 127;
      Qs[q * 132 + d] = wq[((size_t)s * HW + q0 + q) * KD + d];
    }
  }
  if (t < 64) { Om[t] = -1e30f; Ol[t] = 0.0f; }
  {
    int idx = t;
    #pragma unroll
    for (int r = 0; r < 4; r++, idx += 256) Os[idx] = 0.0f;
  }
  __syncthreads();
  int qg = t & 15, kg = t >> 4;
  const float4* qp0 = (const float4*)(Qs + (qg * 4 + 0) * 132);
  const float4* qp1 = (const float4*)(Qs + (qg * 4 + 1) * 132);
  const float4* qp2 = (const float4*)(Qs + (qg * 4 + 2) * 132);
  const float4* qp3 = (const float4*)(Qs + (qg * 4 + 3) * 132);
  const float4* kp0 = (const float4*)(Ks + (kg * 4 + 0) * 132);
  const float4* kp1 = (const float4*)(Ks + (kg * 4 + 1) * 132);
  const float4* kp2 = (const float4*)(Ks + (kg * 4 + 2) * 132);
  const float4* kp3 = (const float4*)(Ks + (kg * 4 + 3) * 132);

  for (int kt = 0; kt < 64; kt++) {
    int kk0 = ksp * 4096 + kt * 64;
    {
      int idx = t;
      #pragma unroll
      for (int r = 0; r < 32; r++, idx += 256) {
        int k = idx >> 7, d = idx & 127;
        Ks[k * 132 + d] = wk[((size_t)s * NM + kk0 + k) * KD + d];
      }
    }
    {
      int f = kk0 >> 10, nn0 = kk0 & 1023;
      const float* pb = pe + ((size_t)(f * S4 + s)) * CE * HW + nn0;
      int idx = t;
      #pragma unroll
      for (int r = 0; r < 4; r++, idx += 256) {
        int e = idx >> 6, k = idx & 63;
        Vs[k * 16 + e] = pb[(size_t)e * HW + k];
      }
    }
    __syncthreads();
    // ---- scores: 4x4 per thread, full 128-d dot via float4 ----
    float acc[4][4] = {};
    #pragma unroll 4
    for (int d4 = 0; d4 < 32; d4++) {
      float4 a0 = qp0[d4], a1 = qp1[d4], a2 = qp2[d4], a3 = qp3[d4];
      float4 b0 = kp0[d4], b1 = kp1[d4], b2 = kp2[d4], b3 = kp3[d4];
      DOT4(acc[0][0], a0, b0); DOT4(acc[0][1], a0, b1);
      DOT4(acc[0][2], a0, b2); DOT4(acc[0][3], a0, b3);
      DOT4(acc[1][0], a1, b0); DOT4(acc[1][1], a1, b1);
      DOT4(acc[1][2], a1, b2); DOT4(acc[1][3], a1, b3);
      DOT4(acc[2][0], a2, b0); DOT4(acc[2][1], a2, b1);
      DOT4(acc[2][2], a2, b2); DOT4(acc[2][3], a2, b3);
      DOT4(acc[3][0], a3, b0); DOT4(acc[3][1], a3, b1);
      DOT4(acc[3][2], a3, b2); DOT4(acc[3][3], a3, b3);
    }
    #pragma unroll
    for (int i = 0; i < 4; i++)
      #pragma unroll
      for (int j = 0; j < 4; j++)
        Ps[(qg * 4 + i) * 65 + kg * 4 + j] = acc[i][j] * TAU_INV;
    __syncthreads();
    // ---- online softmax + V accumulate: warp owns 8 rows ----
    #pragma unroll
    for (int r = 0; r < 8; r++) {
      int q = warp * 8 + r;
      float s0 = Ps[q * 65 + lane], s1 = Ps[q * 65 + 32 + lane];
      float mx = fmaxf(s0, s1);
      #pragma unroll
      for (int o = 16; o; o >>= 1) mx = fmaxf(mx, __shfl_xor_sync(0xffffffffu, mx, o));
      float mo = Om[q];
      float M = fmaxf(mo, mx);
      float p0 = __expf(s0 - M), p1 = __expf(s1 - M);
      float lt = p0 + p1;
      #pragma unroll
      for (int o = 16; o; o >>= 1) lt += __shfl_xor_sync(0xffffffffu, lt, o);
      Ps[q * 65 + lane] = p0; Ps[q * 65 + 32 + lane] = p1;
      __syncwarp();
      float scale = __expf(mo - M);
      int e = lane & 15, kh = (lane >> 4) * 32;
      float o_ = 0.0f;
      #pragma unroll 8
      for (int k2 = 0; k2 < 32; k2++)
        o_ = fmaf(Ps[q * 65 + kh + k2], Vs[(kh + k2) * 16 + e], o_);
      o_ += __shfl_xor_sync(0xffffffffu, o_, 16);
      if (lane < 16) Os[q * 16 + e] = Os[q * 16 + e] * scale + o_;
      if (lane == 0) { Om[q] = M; Ol[q] = Ol[q] * scale + lt; }
      __syncwarp();
    }
    __syncthreads();
  }
  if (t < 64) {
    float* pp = part + ((size_t)((ksp * S4 + s) * HW) + q0 + t) * 18;
    #pragma unroll
    for (int e = 0; e < 16; e++) pp[e] = Os[t * 16 + e];
    pp[16] = Om[t];
    pp[17] = Ol[t];
  }
}

// ================= merge split-K partials + sigmoid =================
__global__ __launch_bounds__(256) void merge_kernel(
    const float* __restrict__ part, float* __restrict__ out) {
  int t = blockIdx.x * 256 + threadIdx.x;  // 4096 threads = (s, n)
  int n = t & 1023, s = t >> 10;
  float M = -1e30f;
  #pragma unroll
  for (int z = 0; z < 4; z++)
    M = fmaxf(M, part[((size_t)((z * S4 + s) * HW) + n) * 18 + 16]);
  float L = 0.0f;
  float O[CE];
  #pragma unroll
  for (int e = 0; e < CE; e++) O[e] = 0.0f;
  #pragma unroll
  for (int z = 0; z < 4; z++) {
    const float* pp = part + ((size_t)((z * S4 + s) * HW) + n) * 18;
    float w = __expf(pp[16] - M);
    L += pp[17] * w;
    #pragma unroll
    for (int e = 0; e < CE; e++) O[e] += pp[e] * w;
  }
  float inv = 1.0f / L;
  #pragma unroll
  for (int e = 0; e < CE; e++) {
    float v = O[e] * inv;
    out[(size_t)(s * CE + e) * HW + n] = 1.0f / (1.0f + __expf(-v));
  }
}

// ================= host =================
extern "C" void kernel_launch(void* const* d_in, const int* in_sizes, int n_in,
                              void* d_out, int out_size) {
  const float* tgt = (const float*)d_in[0];
  const float* mem = (const float*)d_in[1];
  const float* pe  = (const float*)d_in[2];
  const float* wks = (const float*)d_in[3];
  const float* bks = (const float*)d_in[4];
  const float* wkc = (const float*)d_in[5];
  const float* bkc = (const float*)d_in[6];
  float* out = (float*)d_out;

  float *p_wq_self, *p_sc, *p_t, *p_wq_cross, *p_wk_cross, *p_part;
  cudaGetSymbolAddress((void**)&p_wq_self, g_wq_self);
  cudaGetSymbolAddress((void**)&p_sc, g_sc);
  cudaGetSymbolAddress((void**)&p_t, g_t);
  cudaGetSymbolAddress((void**)&p_wq_cross, g_wq_cross);
  cudaGetSymbolAddress((void**)&p_wk_cross, g_wk_cross);
  cudaGetSymbolAddress((void**)&p_part, g_part);

  // self-attention
  proj_kernel<<<dim3(32, 4), 256>>>(tgt, wks, bks, p_wq_self, HW);
  self_scores_kernel<<<dim3(16, 16, 4), 256>>>(p_wq_self, p_sc);
  softmax_kernel<<<4096, 256>>>(p_sc);
  pv_self_kernel<<<dim3(16, 8, 4), 256>>>(p_sc, tgt, p_t);
  instnorm_kernel<<<2048, 256>>>(p_t);

  // cross-attention projections
  proj_kernel<<<dim3(32, 4), 256>>>(p_t, wkc, bkc, p_wq_cross, HW);
  proj_kernel<<<dim3(512, 4), 256>>>(mem, wkc, bkc, p_wk_cross, NM);

  // flash cross-attention with split-K=4
  static const size_t smem_bytes = (size_t)(64 * 132 * 2 + 64 * 65 + 64 * 16 * 2 + 128) * 4;
  cudaFuncSetAttribute(cross_attn_kernel,
                       cudaFuncAttributeMaxDynamicSharedMemorySize, 98304);
  cross_attn_kernel<<<dim3(16, 4, 4), 256, smem_bytes>>>(p_wq_cross, p_wk_cross, pe, p_part);
  merge_kernel<<<16, 256>>>(p_part, out);
}